// round 13
// baseline (speedup 1.0000x reference)
#include <cuda_runtime.h>
#include <cuda_bf16.h>
#include <cuda_fp16.h>
#include <mma.h>
#include <cstdint>
#include <cstdio>

using namespace nvcuda;

// ---------------- Problem constants ----------------
#define T_LEN   1024
#define HID     1024
#define H_HEADS 32
#define P_DIM   64
#define N_STATE 128
#define NL      15
#define KCONV   4
#define INTER   2048          // H*P
#define CONV_DIM 2304         // INTER + 2*N
#define PROJ    4864          // INTER + CONV_DIM + H*(NL+1)
#define DT_OFF  4352          // INTER + CONV_DIM
#define EPSNRM  1e-5f

// ---------------- Scratch (device globals; no allocation allowed) ----------------
__device__ float g_zx[T_LEN * PROJ];        // in_proj output (bias fused in consumers)
__device__ float g_x[T_LEN * INTER];        // conv+silu x part (unscaled)
__device__ float g_dt[T_LEN * H_HEADS];     // softplus dt, [t][h]
__device__ float g_g[H_HEADS * T_LEN];      // per-step log decay, [h][t]
__device__ float g_cg[H_HEADS * T_LEN];     // cumsum, [h][t]
__device__ float g_Ls[T_LEN * H_HEADS * NL];// level scales [t][h][l]
__device__ float g_scores[T_LEN * T_LEN];   // C·B^T (head-independent, G=1)
__device__ float g_y[T_LEN * INTER];        // attention output (D residual fused later)

// fp16 operands
__device__ __half g_hsh[T_LEN * HID],  g_hsl[T_LEN * HID];   // hs hi/lo
__device__ __half g_w1[PROJ * HID];                          // w1 single
__device__ __half g_w2[HID * INTER];                         // w2 single
__device__ __half g_Bm16[T_LEN * N_STATE];                   // keys single
__device__ __half g_Ch[T_LEN * N_STATE], g_Cl[T_LEN * N_STATE]; // queries hi/lo
__device__ __half g_ynh[T_LEN * INTER],  g_ynl[T_LEN * INTER];  // yn hi/lo
__device__ __half g_vh[T_LEN * INTER],   g_vl[T_LEN * INTER];   // v = x*dt hi/lo

__device__ __forceinline__ float softplus_f(float x) {
    return (x > 20.f) ? x : log1pf(expf(x));
}
__device__ __forceinline__ float silu_f(float x) {
    return x / (1.f + expf(-x));
}
__device__ __forceinline__ void split_fp16(float x, __half& h, __half& l) {
    h = __float2half(x);
    l = __float2half(x - __half2float(h));
}

#define CP_ASYNC16(smem_u32, gptr) \
    asm volatile("cp.async.cg.shared.global [%0], [%1], 16;\n" :: "r"(smem_u32), "l"(gptr))
#define CP_COMMIT() asm volatile("cp.async.commit_group;\n" ::: "memory")
#define CP_WAIT(n)  asm volatile("cp.async.wait_group %0;\n" :: "n"(n) : "memory")

// ---------------- fp32 -> fp16 hi/lo split, 8 elems/thread ----------------
__global__ void split_pair_kernel(const float* __restrict__ src,
                                  __half* __restrict__ hi,
                                  __half* __restrict__ lo, int n) {
    int i = (blockIdx.x * blockDim.x + threadIdx.x) * 8;
    if (i >= n) return;
    float4 a = *(const float4*)(src + i);
    float4 b = *(const float4*)(src + i + 4);
    __half hh[8], ll[8];
    const float v[8] = {a.x, a.y, a.z, a.w, b.x, b.y, b.z, b.w};
#pragma unroll
    for (int k = 0; k < 8; k++) split_fp16(v[k], hh[k], ll[k]);
    *(uint4*)(hi + i) = *(const uint4*)hh;
    *(uint4*)(lo + i) = *(const uint4*)ll;
}

// ---------------- fp32 -> fp16 single convert, 8 elems/thread ----------------
__global__ void cvt_fp16_kernel(const float* __restrict__ src,
                                __half* __restrict__ dst, int n) {
    int i = (blockIdx.x * blockDim.x + threadIdx.x) * 8;
    if (i >= n) return;
    float4 a = *(const float4*)(src + i);
    float4 b = *(const float4*)(src + i + 4);
    __half hh[8];
    const float v[8] = {a.x, a.y, a.z, a.w, b.x, b.y, b.z, b.w};
#pragma unroll
    for (int k = 0; k < 8; k++) hh[k] = __float2half(v[k]);
    *(uint4*)(dst + i) = *(const uint4*)hh;
}

// ---------------- bias add (final output epilogue), float4 ----------------
__global__ void bias_add_kernel(float* __restrict__ C, const float* __restrict__ bias,
                                int N, int total) {
    int i = (blockIdx.x * blockDim.x + threadIdx.x) * 4;
    if (i >= total) return;
    float4 v = *(const float4*)(C + i);
    float4 bv = *(const float4*)(bias + (i % N));
    v.x += bv.x; v.y += bv.y; v.z += bv.z; v.w += bv.w;
    *(float4*)(C + i) = v;
}

// ---------------- Tensor-core NT GEMM, fp16 A-compensated x2 ----------------
template <int BN>
__global__ __launch_bounds__(256, 2)
void gemm_fp16x2_nt(const __half* __restrict__ Ah, const __half* __restrict__ Al,
                    const __half* __restrict__ B,
                    float* __restrict__ C, int M, int N, int K) {
    constexpr int NF = BN / 32;
    __shared__ __half sA[2][2][128][40];
    __shared__ __half sB[2][BN][40];
    const int tid = threadIdx.x;
    const int bm = blockIdx.y * 128, bn = blockIdx.x * BN;
    const int warp = tid >> 5;
    const int wm = (warp & 3) * 32;
    const int wn = (warp >> 2) * (BN / 2);

    wmma::fragment<wmma::accumulator, 16, 16, 16, float> acc[2][NF];
#pragma unroll
    for (int i = 0; i < 2; i++)
#pragma unroll
        for (int j = 0; j < NF; j++) wmma::fill_fragment(acc[i][j], 0.f);

    const int lr = tid >> 2;
    const int lc = (tid & 3) * 8;

    auto load_stage = [&](int k0, int buf) {
#pragma unroll
        for (int r = 0; r < 128; r += 64) {
            const size_t aoff = (size_t)(bm + lr + r) * K + k0 + lc;
            CP_ASYNC16((unsigned)__cvta_generic_to_shared(&sA[buf][0][lr + r][lc]), Ah + aoff);
            CP_ASYNC16((unsigned)__cvta_generic_to_shared(&sA[buf][1][lr + r][lc]), Al + aoff);
        }
#pragma unroll
        for (int r = 0; r < BN; r += 64) {
            const size_t boff = (size_t)(bn + lr + r) * K + k0 + lc;
            CP_ASYNC16((unsigned)__cvta_generic_to_shared(&sB[buf][lr + r][lc]), B + boff);
        }
    };

    load_stage(0, 0);
    CP_COMMIT();

    const int nt = K >> 5;
    for (int kt = 0; kt < nt; kt++) {
        const int buf = kt & 1;
        if (kt + 1 < nt) {
            load_stage((kt + 1) << 5, buf ^ 1);
            CP_COMMIT();
            CP_WAIT(1);
        } else {
            CP_WAIT(0);
        }
        __syncthreads();
#pragma unroll
        for (int ks = 0; ks < 32; ks += 16) {
            wmma::fragment<wmma::matrix_a, 16, 16, 16, __half, wmma::row_major> ah[2], al[2];
#pragma unroll
            for (int i = 0; i < 2; i++) {
                wmma::load_matrix_sync(ah[i], &sA[buf][0][wm + 16 * i][ks], 40);
                wmma::load_matrix_sync(al[i], &sA[buf][1][wm + 16 * i][ks], 40);
            }
#pragma unroll
            for (int j = 0; j < NF; j++) {
                wmma::fragment<wmma::matrix_b, 16, 16, 16, __half, wmma::col_major> bf;
                wmma::load_matrix_sync(bf, &sB[buf][wn + 16 * j][ks], 40);
                wmma::mma_sync(acc[0][j], ah[0], bf, acc[0][j]);
                wmma::mma_sync(acc[1][j], ah[1], bf, acc[1][j]);
                wmma::mma_sync(acc[0][j], al[0], bf, acc[0][j]);
                wmma::mma_sync(acc[1][j], al[1], bf, acc[1][j]);
            }
        }
        __syncthreads();
    }
#pragma unroll
    for (int i = 0; i < 2; i++)
#pragma unroll
        for (int j = 0; j < NF; j++)
            wmma::store_matrix_sync(C + (size_t)(bm + wm + 16 * i) * N + bn + wn + 16 * j,
                                    acc[i][j], N, wmma::mem_row_major);
}

// ---------------- dt / g / Ls prep (b1 fused) — runs BEFORE conv ----------------
__global__ void prep_kernel(const float* __restrict__ dt_bias,
                            const float* __restrict__ A_log,
                            const float* __restrict__ L_param,
                            const float* __restrict__ b1) {
    int t = blockIdx.x;
    const float* row = g_zx + (size_t)t * PROJ + DT_OFF;
    const float* brow = b1 + DT_OFF;
    for (int i = threadIdx.x; i < H_HEADS; i += blockDim.x) {
        float d = softplus_f(row[i] + brow[i] + dt_bias[i]);
        g_dt[t * H_HEADS + i] = d;
        g_g[i * T_LEN + t] = -expf(A_log[i]) * d;
    }
    for (int i = threadIdx.x; i < H_HEADS * NL; i += blockDim.x) {
        g_Ls[(size_t)t * (H_HEADS * NL) + i] =
            softplus_f(L_param[i] * (row[H_HEADS + i] + brow[H_HEADS + i]));
    }
}

// ---------------- Depthwise conv (K=4) + SiLU, sliding window 8 t/thread ----------------
// Also emits v = x*dt as fp16 hi/lo (dt from prep, which runs first).
__global__ void conv_silu_kernel(const float* __restrict__ conv_w,
                                 const float* __restrict__ b1) {
    int idx = blockIdx.x * blockDim.x + threadIdx.x;
    if (idx >= CONV_DIM * (T_LEN / 8)) return;
    const int c  = idx % CONV_DIM;
    const int t0 = (idx / CONV_DIM) * 8;
    const float bias = b1[INTER + c];
    float w0 = conv_w[c * KCONV + 0], w1_ = conv_w[c * KCONV + 1];
    float w2_ = conv_w[c * KCONV + 2], w3 = conv_w[c * KCONV + 3];
    float win[11];
#pragma unroll
    for (int i = 0; i < 11; i++) {
        int ts = t0 - 3 + i;
        win[i] = (ts >= 0) ? g_zx[(size_t)ts * PROJ + INTER + c] + bias : 0.f;
    }
#pragma unroll
    for (int k = 0; k < 8; k++) {
        const int t = t0 + k;
        float acc = win[k] * w0 + win[k + 1] * w1_ + win[k + 2] * w2_ + win[k + 3] * w3;
        float s = silu_f(acc);
        if (c < INTER) {
            g_x[(size_t)t * INTER + c] = s;
            float v = s * g_dt[t * H_HEADS + (c >> 6)];
            __half h, l; split_fp16(v, h, l);
            g_vh[(size_t)t * INTER + c] = h;
            g_vl[(size_t)t * INTER + c] = l;
        } else if (c < INTER + N_STATE) {
            g_Bm16[t * N_STATE + (c - INTER)] = __float2half(s);
        } else {
            __half h, l; split_fp16(s, h, l);
            int o = t * N_STATE + (c - INTER - N_STATE);
            g_Ch[o] = h; g_Cl[o] = l;
        }
    }
}

// ---------------- inclusive scan of g over t, per head ----------------
__global__ __launch_bounds__(1024)
void scan_kernel() {
    __shared__ float sh[T_LEN];
    int h = blockIdx.x;
    int t = threadIdx.x;
    sh[t] = g_g[h * T_LEN + t];
    __syncthreads();
    for (int off = 1; off < T_LEN; off <<= 1) {
        float add = (t >= off) ? sh[t - off] : 0.f;
        __syncthreads();
        sh[t] += add;
        __syncthreads();
    }
    g_cg[h * T_LEN + t] = sh[t];
}

// ---------------- Attention on tensor cores: per (head, t-tile of 64) ----------------
// w[t,s] = scores * exp(cg_t - cg_s) * Ls[t,lvl] built in smem (fp16 hi/lo);
// v fragments loaded DIRECTLY from gmem (g_vh/g_vl, L2-hot).
__global__ __launch_bounds__(256)
void attn_tc_kernel(const int* __restrict__ lvl) {
    const int h = blockIdx.y;
    const int t0 = blockIdx.x * 64;
    __shared__ __half s_wh[64][72], s_wl[64][72];
    __shared__ float s_cgt[64], s_cgs[64];
    __shared__ float s_Lst[64][16];
    const int tid = threadIdx.x;
    const int warp = tid >> 5;
    const int wm = (warp & 3) * 16;      // 4 warps along t
    const int wn = (warp >> 2) * 32;     // 2 warps along p

    if (tid < 64) s_cgt[tid] = g_cg[h * T_LEN + t0 + tid];
    for (int i = tid; i < 64 * NL; i += 256) {
        int r = i / NL, l = i % NL;
        s_Lst[r][l] = g_Ls[((size_t)(t0 + r) * H_HEADS + h) * NL + l];
    }

    wmma::fragment<wmma::accumulator, 16, 16, 16, float> acc[2];
    wmma::fill_fragment(acc[0], 0.f);
    wmma::fill_fragment(acc[1], 0.f);

    const __half* vhp = g_vh + h * P_DIM + wn;
    const __half* vlp = g_vl + h * P_DIM + wn;

    for (int s0 = 0; s0 <= t0; s0 += 64) {
        __syncthreads();   // protect s_w from previous iteration's MMA reads
        if (s0 < t0) {
            float maxld = g_cg[h * T_LEN + t0] - g_cg[h * T_LEN + s0 + 63];
            if (maxld < -30.f) continue;
        }
        if (tid < 64) s_cgs[tid] = g_cg[h * T_LEN + s0 + tid];
        __syncthreads();
        // build w tile (fp16 pair)
        for (int i = tid; i < 64 * 64; i += 256) {
            int r = i >> 6, c = i & 63;
            int tg = t0 + r, sg = s0 + c;
            float w = 0.f;
            if (sg <= tg) {
                int L = lvl[(size_t)tg * T_LEN + sg];
                w = g_scores[(size_t)tg * T_LEN + sg] *
                    __expf(s_cgt[r] - s_cgs[c]) * s_Lst[r][L];
            }
            __half hh, ll; split_fp16(w, hh, ll);
            s_wh[r][c] = hh; s_wl[r][c] = ll;
        }
        __syncthreads();
        // acc += w @ v (3-pass compensated), v fragments straight from gmem
#pragma unroll
        for (int ks = 0; ks < 64; ks += 16) {
            wmma::fragment<wmma::matrix_a, 16, 16, 16, __half, wmma::row_major> ah, al;
            wmma::load_matrix_sync(ah, &s_wh[wm][ks], 72);
            wmma::load_matrix_sync(al, &s_wl[wm][ks], 72);
            const size_t vrow = (size_t)(s0 + ks) * INTER;
#pragma unroll
            for (int j = 0; j < 2; j++) {
                wmma::fragment<wmma::matrix_b, 16, 16, 16, __half, wmma::row_major> bh, bl;
                wmma::load_matrix_sync(bh, vhp + vrow + 16 * j, INTER);
                wmma::load_matrix_sync(bl, vlp + vrow + 16 * j, INTER);
                wmma::mma_sync(acc[j], ah, bh, acc[j]);
                wmma::mma_sync(acc[j], al, bh, acc[j]);
                wmma::mma_sync(acc[j], ah, bl, acc[j]);
            }
        }
    }
#pragma unroll
    for (int j = 0; j < 2; j++)
        wmma::store_matrix_sync(
            g_y + (size_t)(t0 + wm) * INTER + h * P_DIM + wn + 16 * j,
            acc[j], INTER, wmma::mem_row_major);
}

// ---------------- gated RMSNorm (b1 + D residual fused), fp16 hi/lo out ----------------
__global__ __launch_bounds__(256)
void gated_norm_kernel(const float* __restrict__ rmsw, const float* __restrict__ b1,
                       const float* __restrict__ Dp) {
    const int t = blockIdx.x;
    __shared__ float red[8];
    float vals[8];
    float local = 0.f;
#pragma unroll
    for (int i = 0; i < 8; i++) {
        int c = threadIdx.x + i * 256;
        float z = g_zx[(size_t)t * PROJ + c] + b1[c];
        float yv = g_y[(size_t)t * INTER + c] +
                   g_x[(size_t)t * INTER + c] * Dp[c >> 6];
        float gv = yv * silu_f(z);
        vals[i] = gv;
        local = fmaf(gv, gv, local);
    }
#pragma unroll
    for (int off = 16; off > 0; off >>= 1)
        local += __shfl_xor_sync(0xffffffffu, local, off);
    if ((threadIdx.x & 31) == 0) red[threadIdx.x >> 5] = local;
    __syncthreads();
    if (threadIdx.x < 8) {
        float v = red[threadIdx.x];
#pragma unroll
        for (int off = 4; off > 0; off >>= 1)
            v += __shfl_xor_sync(0xffu, v, off);
        if (threadIdx.x == 0) red[0] = v;
    }
    __syncthreads();
    const float inv = rsqrtf(red[0] / (float)INTER + EPSNRM);
#pragma unroll
    for (int i = 0; i < 8; i++) {
        int c = threadIdx.x + i * 256;
        float v = vals[i] * inv * rmsw[c];
        __half h, l; split_fp16(v, h, l);
        g_ynh[(size_t)t * INTER + c] = h;
        g_ynl[(size_t)t * INTER + c] = l;
    }
}

// ---------------- Launch ----------------
extern "C" void kernel_launch(void* const* d_in, const int* in_sizes, int n_in,
                              void* d_out, int out_size) {
    const float* hs    = (const float*)d_in[0];
    const float* w1    = (const float*)d_in[1];
    const float* b1    = (const float*)d_in[2];
    const float* cw    = (const float*)d_in[3];
    const float* dtb   = (const float*)d_in[4];
    const float* alog  = (const float*)d_in[5];
    const float* lpar  = (const float*)d_in[6];
    const float* Dp    = (const float*)d_in[7];
    const float* rmsw  = (const float*)d_in[8];
    const float* w2    = (const float*)d_in[9];
    const float* b2    = (const float*)d_in[10];
    const int*   lvl   = (const int*)d_in[11];
    float* out = (float*)d_out;

    float *zx, *scores;
    __half *hsh, *hsl, *w1p, *w2p, *Bm16, *Ch, *Cl, *ynh, *ynl;
    cudaGetSymbolAddress((void**)&zx, g_zx);
    cudaGetSymbolAddress((void**)&scores, g_scores);
    cudaGetSymbolAddress((void**)&hsh, g_hsh);  cudaGetSymbolAddress((void**)&hsl, g_hsl);
    cudaGetSymbolAddress((void**)&w1p, g_w1);   cudaGetSymbolAddress((void**)&w2p, g_w2);
    cudaGetSymbolAddress((void**)&Bm16, g_Bm16);
    cudaGetSymbolAddress((void**)&Ch, g_Ch);    cudaGetSymbolAddress((void**)&Cl, g_Cl);
    cudaGetSymbolAddress((void**)&ynh, g_ynh);  cudaGetSymbolAddress((void**)&ynl, g_ynl);

    // 0) operand conversion (8 elems/thread)
    split_pair_kernel<<<(T_LEN * HID / 8 + 255) / 256, 256>>>(hs, hsh, hsl, T_LEN * HID);
    cvt_fp16_kernel<<<(PROJ * HID / 8 + 255) / 256, 256>>>(w1, w1p, PROJ * HID);
    cvt_fp16_kernel<<<(HID * INTER / 8 + 255) / 256, 256>>>(w2, w2p, HID * INTER);

    // 1) in_proj
    gemm_fp16x2_nt<128><<<dim3(PROJ / 128, T_LEN / 128), 256>>>(hsh, hsl, w1p, zx,
                                                                T_LEN, PROJ, HID);

    // 2) dt / g / Ls (before conv: conv needs dt for the v split)
    prep_kernel<<<T_LEN, 128>>>(dtb, alog, lpar, b1);

    // 3) conv + silu + splits (x, v pair, B, C pair)
    conv_silu_kernel<<<(CONV_DIM * (T_LEN / 8) + 255) / 256, 256>>>(cw, b1);

    // 4) cumsum of g per head
    scan_kernel<<<H_HEADS, 1024>>>();

    // 5) scores[t,s] = C[t]·B[s]
    gemm_fp16x2_nt<64><<<dim3(T_LEN / 64, T_LEN / 128), 256>>>(Ch, Cl, Bm16, scores,
                                                               T_LEN, T_LEN, N_STATE);

    // 6) attention (tensor-core w@v, v from gmem)
    attn_tc_kernel<<<dim3(T_LEN / 64, H_HEADS), 256>>>(lvl);

    // 7) gated RMSNorm (D residual + b1 fused)
    gated_norm_kernel<<<T_LEN, 256>>>(rmsw, b1, Dp);

    // 8) out_proj
    gemm_fp16x2_nt<64><<<dim3(HID / 64, T_LEN / 128), 256>>>(ynh, ynl, w2p, out,
                                                             T_LEN, HID, INTER);
    bias_add_kernel<<<(T_LEN * HID / 4 + 255) / 256, 256>>>(out, b2, HID, T_LEN * HID);
}

// round 14
// speedup vs baseline: 1.6220x; 1.6220x over previous
#include <cuda_runtime.h>
#include <cuda_bf16.h>
#include <cuda_fp16.h>
#include <mma.h>
#include <cstdint>
#include <cstdio>

using namespace nvcuda;

// ---------------- Problem constants ----------------
#define T_LEN   1024
#define HID     1024
#define H_HEADS 32
#define P_DIM   64
#define N_STATE 128
#define NL      15
#define KCONV   4
#define INTER   2048          // H*P
#define CONV_DIM 2304         // INTER + 2*N
#define PROJ    4864          // INTER + CONV_DIM + H*(NL+1)
#define DT_OFF  4352          // INTER + CONV_DIM
#define EPSNRM  1e-5f

// ---------------- Scratch (device globals; no allocation allowed) ----------------
__device__ float g_zx[T_LEN * PROJ];        // in_proj output (bias fused in consumers)
__device__ float g_x[T_LEN * INTER];        // conv+silu x part (unscaled)
__device__ float g_dt[T_LEN * H_HEADS];     // softplus dt, [t][h]
__device__ float g_g[H_HEADS * T_LEN];      // per-step log decay, [h][t]
__device__ float g_cg[H_HEADS * T_LEN];     // cumsum, [h][t]
__device__ float g_Ls[T_LEN * H_HEADS * NL];// level scales [t][h][l]
__device__ float g_scores[T_LEN * T_LEN];   // C·B^T (head-independent, G=1)
__device__ float g_y[T_LEN * INTER];        // attention output (D residual fused later)

// fp16 operands
__device__ __half g_hsh[T_LEN * HID],  g_hsl[T_LEN * HID];   // hs hi/lo
__device__ __half g_w1[PROJ * HID];                          // w1 single
__device__ __half g_w2[HID * INTER];                         // w2 single
__device__ __half g_Bm16[T_LEN * N_STATE];                   // keys single
__device__ __half g_Ch[T_LEN * N_STATE], g_Cl[T_LEN * N_STATE]; // queries hi/lo
__device__ __half g_ynh[T_LEN * INTER],  g_ynl[T_LEN * INTER];  // yn hi/lo
__device__ __half g_vh[T_LEN * INTER],   g_vl[T_LEN * INTER];   // v = x*dt hi/lo

__device__ __forceinline__ float softplus_f(float x) {
    return (x > 20.f) ? x : log1pf(expf(x));
}
__device__ __forceinline__ float silu_f(float x) {
    return x / (1.f + expf(-x));
}
__device__ __forceinline__ void split_fp16(float x, __half& h, __half& l) {
    h = __float2half(x);
    l = __float2half(x - __half2float(h));
}

#define CP_ASYNC16(smem_u32, gptr) \
    asm volatile("cp.async.cg.shared.global [%0], [%1], 16;\n" :: "r"(smem_u32), "l"(gptr))
#define CP_COMMIT() asm volatile("cp.async.commit_group;\n" ::: "memory")
#define CP_WAIT(n)  asm volatile("cp.async.wait_group %0;\n" :: "n"(n) : "memory")

// ---------------- fp32 -> fp16 hi/lo split, 8 elems/thread ----------------
__global__ void split_pair_kernel(const float* __restrict__ src,
                                  __half* __restrict__ hi,
                                  __half* __restrict__ lo, int n) {
    int i = (blockIdx.x * blockDim.x + threadIdx.x) * 8;
    if (i >= n) return;
    float4 a = *(const float4*)(src + i);
    float4 b = *(const float4*)(src + i + 4);
    __half hh[8], ll[8];
    const float v[8] = {a.x, a.y, a.z, a.w, b.x, b.y, b.z, b.w};
#pragma unroll
    for (int k = 0; k < 8; k++) split_fp16(v[k], hh[k], ll[k]);
    *(uint4*)(hi + i) = *(const uint4*)hh;
    *(uint4*)(lo + i) = *(const uint4*)ll;
}

// ---------------- fp32 -> fp16 single convert, 8 elems/thread ----------------
__global__ void cvt_fp16_kernel(const float* __restrict__ src,
                                __half* __restrict__ dst, int n) {
    int i = (blockIdx.x * blockDim.x + threadIdx.x) * 8;
    if (i >= n) return;
    float4 a = *(const float4*)(src + i);
    float4 b = *(const float4*)(src + i + 4);
    __half hh[8];
    const float v[8] = {a.x, a.y, a.z, a.w, b.x, b.y, b.z, b.w};
#pragma unroll
    for (int k = 0; k < 8; k++) hh[k] = __float2half(v[k]);
    *(uint4*)(dst + i) = *(const uint4*)hh;
}

// ---------------- bias add (final output epilogue), float4 ----------------
__global__ void bias_add_kernel(float* __restrict__ C, const float* __restrict__ bias,
                                int N, int total) {
    int i = (blockIdx.x * blockDim.x + threadIdx.x) * 4;
    if (i >= total) return;
    float4 v = *(const float4*)(C + i);
    float4 bv = *(const float4*)(bias + (i % N));
    v.x += bv.x; v.y += bv.y; v.z += bv.z; v.w += bv.w;
    *(float4*)(C + i) = v;
}

// ---------------- Tensor-core NT GEMM, fp16 A-compensated x2 ----------------
template <int BN>
__global__ __launch_bounds__(256, 2)
void gemm_fp16x2_nt(const __half* __restrict__ Ah, const __half* __restrict__ Al,
                    const __half* __restrict__ B,
                    float* __restrict__ C, int M, int N, int K) {
    constexpr int NF = BN / 32;
    __shared__ __half sA[2][2][128][40];
    __shared__ __half sB[2][BN][40];
    const int tid = threadIdx.x;
    const int bm = blockIdx.y * 128, bn = blockIdx.x * BN;
    const int warp = tid >> 5;
    const int wm = (warp & 3) * 32;
    const int wn = (warp >> 2) * (BN / 2);

    wmma::fragment<wmma::accumulator, 16, 16, 16, float> acc[2][NF];
#pragma unroll
    for (int i = 0; i < 2; i++)
#pragma unroll
        for (int j = 0; j < NF; j++) wmma::fill_fragment(acc[i][j], 0.f);

    const int lr = tid >> 2;
    const int lc = (tid & 3) * 8;

    auto load_stage = [&](int k0, int buf) {
#pragma unroll
        for (int r = 0; r < 128; r += 64) {
            const size_t aoff = (size_t)(bm + lr + r) * K + k0 + lc;
            CP_ASYNC16((unsigned)__cvta_generic_to_shared(&sA[buf][0][lr + r][lc]), Ah + aoff);
            CP_ASYNC16((unsigned)__cvta_generic_to_shared(&sA[buf][1][lr + r][lc]), Al + aoff);
        }
#pragma unroll
        for (int r = 0; r < BN; r += 64) {
            const size_t boff = (size_t)(bn + lr + r) * K + k0 + lc;
            CP_ASYNC16((unsigned)__cvta_generic_to_shared(&sB[buf][lr + r][lc]), B + boff);
        }
    };

    load_stage(0, 0);
    CP_COMMIT();

    const int nt = K >> 5;
    for (int kt = 0; kt < nt; kt++) {
        const int buf = kt & 1;
        if (kt + 1 < nt) {
            load_stage((kt + 1) << 5, buf ^ 1);
            CP_COMMIT();
            CP_WAIT(1);
        } else {
            CP_WAIT(0);
        }
        __syncthreads();
#pragma unroll
        for (int ks = 0; ks < 32; ks += 16) {
            wmma::fragment<wmma::matrix_a, 16, 16, 16, __half, wmma::row_major> ah[2], al[2];
#pragma unroll
            for (int i = 0; i < 2; i++) {
                wmma::load_matrix_sync(ah[i], &sA[buf][0][wm + 16 * i][ks], 40);
                wmma::load_matrix_sync(al[i], &sA[buf][1][wm + 16 * i][ks], 40);
            }
#pragma unroll
            for (int j = 0; j < NF; j++) {
                wmma::fragment<wmma::matrix_b, 16, 16, 16, __half, wmma::col_major> bf;
                wmma::load_matrix_sync(bf, &sB[buf][wn + 16 * j][ks], 40);
                wmma::mma_sync(acc[0][j], ah[0], bf, acc[0][j]);
                wmma::mma_sync(acc[1][j], ah[1], bf, acc[1][j]);
                wmma::mma_sync(acc[0][j], al[0], bf, acc[0][j]);
                wmma::mma_sync(acc[1][j], al[1], bf, acc[1][j]);
            }
        }
        __syncthreads();
    }
#pragma unroll
    for (int i = 0; i < 2; i++)
#pragma unroll
        for (int j = 0; j < NF; j++)
            wmma::store_matrix_sync(C + (size_t)(bm + wm + 16 * i) * N + bn + wn + 16 * j,
                                    acc[i][j], N, wmma::mem_row_major);
}

// ---------------- dt / g / Ls prep (b1 fused) — runs BEFORE conv ----------------
__global__ void prep_kernel(const float* __restrict__ dt_bias,
                            const float* __restrict__ A_log,
                            const float* __restrict__ L_param,
                            const float* __restrict__ b1) {
    int t = blockIdx.x;
    const float* row = g_zx + (size_t)t * PROJ + DT_OFF;
    const float* brow = b1 + DT_OFF;
    for (int i = threadIdx.x; i < H_HEADS; i += blockDim.x) {
        float d = softplus_f(row[i] + brow[i] + dt_bias[i]);
        g_dt[t * H_HEADS + i] = d;
        g_g[i * T_LEN + t] = -expf(A_log[i]) * d;
    }
    for (int i = threadIdx.x; i < H_HEADS * NL; i += blockDim.x) {
        g_Ls[(size_t)t * (H_HEADS * NL) + i] =
            softplus_f(L_param[i] * (row[H_HEADS + i] + brow[H_HEADS + i]));
    }
}

// ---------------- Depthwise conv (K=4) + SiLU, sliding window 8 t/thread ----------------
// Also emits v = x*dt as fp16 hi/lo (dt from prep, which runs first).
__global__ void conv_silu_kernel(const float* __restrict__ conv_w,
                                 const float* __restrict__ b1) {
    int idx = blockIdx.x * blockDim.x + threadIdx.x;
    if (idx >= CONV_DIM * (T_LEN / 8)) return;
    const int c  = idx % CONV_DIM;
    const int t0 = (idx / CONV_DIM) * 8;
    const float bias = b1[INTER + c];
    float w0 = conv_w[c * KCONV + 0], w1_ = conv_w[c * KCONV + 1];
    float w2_ = conv_w[c * KCONV + 2], w3 = conv_w[c * KCONV + 3];
    float win[11];
#pragma unroll
    for (int i = 0; i < 11; i++) {
        int ts = t0 - 3 + i;
        win[i] = (ts >= 0) ? g_zx[(size_t)ts * PROJ + INTER + c] + bias : 0.f;
    }
#pragma unroll
    for (int k = 0; k < 8; k++) {
        const int t = t0 + k;
        float acc = win[k] * w0 + win[k + 1] * w1_ + win[k + 2] * w2_ + win[k + 3] * w3;
        float s = silu_f(acc);
        if (c < INTER) {
            g_x[(size_t)t * INTER + c] = s;
            float v = s * g_dt[t * H_HEADS + (c >> 6)];
            __half h, l; split_fp16(v, h, l);
            g_vh[(size_t)t * INTER + c] = h;
            g_vl[(size_t)t * INTER + c] = l;
        } else if (c < INTER + N_STATE) {
            g_Bm16[t * N_STATE + (c - INTER)] = __float2half(s);
        } else {
            __half h, l; split_fp16(s, h, l);
            int o = t * N_STATE + (c - INTER - N_STATE);
            g_Ch[o] = h; g_Cl[o] = l;
        }
    }
}

// ---------------- inclusive scan of g over t, per head ----------------
__global__ __launch_bounds__(1024)
void scan_kernel() {
    __shared__ float sh[T_LEN];
    int h = blockIdx.x;
    int t = threadIdx.x;
    sh[t] = g_g[h * T_LEN + t];
    __syncthreads();
    for (int off = 1; off < T_LEN; off <<= 1) {
        float add = (t >= off) ? sh[t - off] : 0.f;
        __syncthreads();
        sh[t] += add;
        __syncthreads();
    }
    g_cg[h * T_LEN + t] = sh[t];
}

// ---------------- Attention on tensor cores: per (head, t-tile of 64) ----------------
// w[t,s] built in smem as fp16 hi/lo; v tiles cp.async'ed from precomputed g_vh/g_vl.
__global__ __launch_bounds__(256)
void attn_tc_kernel(const int* __restrict__ lvl) {
    const int h = blockIdx.y;
    const int t0 = blockIdx.x * 64;
    __shared__ __half s_wh[64][72], s_wl[64][72];
    __shared__ __half s_vh[64][72], s_vl[64][72];
    __shared__ float s_cgt[64], s_cgs[64];
    __shared__ float s_Lst[64][16];
    const int tid = threadIdx.x;
    const int warp = tid >> 5;
    const int wm = (warp & 3) * 16;      // 4 warps along t
    const int wn = (warp >> 2) * 32;     // 2 warps along p

    if (tid < 64) s_cgt[tid] = g_cg[h * T_LEN + t0 + tid];
    for (int i = tid; i < 64 * NL; i += 256) {
        int r = i / NL, l = i % NL;
        s_Lst[r][l] = g_Ls[((size_t)(t0 + r) * H_HEADS + h) * NL + l];
    }

    wmma::fragment<wmma::accumulator, 16, 16, 16, float> acc[2];
    wmma::fill_fragment(acc[0], 0.f);
    wmma::fill_fragment(acc[1], 0.f);

    for (int s0 = 0; s0 <= t0; s0 += 64) {
        __syncthreads();   // protect smem from previous iteration's MMA reads
        if (s0 < t0) {
            float maxld = g_cg[h * T_LEN + t0] - g_cg[h * T_LEN + s0 + 63];
            if (maxld < -30.f) continue;
        }
        if (tid < 64) s_cgs[tid] = g_cg[h * T_LEN + s0 + tid];
        // v tiles: async copy from precomputed fp16 pairs (coalesced 16B chunks)
        {
            // 64 rows x 64 halves = 64 x 8 chunks per array; 512 chunks each
            for (int i = tid; i < 512; i += 256) {
                int r = i >> 3, ch = (i & 7) * 8;
                const size_t goff = (size_t)(s0 + r) * INTER + h * P_DIM + ch;
                CP_ASYNC16((unsigned)__cvta_generic_to_shared(&s_vh[r][ch]), g_vh + goff);
                CP_ASYNC16((unsigned)__cvta_generic_to_shared(&s_vl[r][ch]), g_vl + goff);
            }
            CP_COMMIT();
        }
        __syncthreads();
        // build w tile (fp16 pair)
        for (int i = tid; i < 64 * 64; i += 256) {
            int r = i >> 6, c = i & 63;
            int tg = t0 + r, sg = s0 + c;
            float w = 0.f;
            if (sg <= tg) {
                int L = lvl[(size_t)tg * T_LEN + sg];
                w = g_scores[(size_t)tg * T_LEN + sg] *
                    __expf(s_cgt[r] - s_cgs[c]) * s_Lst[r][L];
            }
            __half hh, ll; split_fp16(w, hh, ll);
            s_wh[r][c] = hh; s_wl[r][c] = ll;
        }
        CP_WAIT(0);
        __syncthreads();
        // acc += w @ v  (3-pass compensated)
#pragma unroll
        for (int ks = 0; ks < 64; ks += 16) {
            wmma::fragment<wmma::matrix_a, 16, 16, 16, __half, wmma::row_major> ah, al;
            wmma::load_matrix_sync(ah, &s_wh[wm][ks], 72);
            wmma::load_matrix_sync(al, &s_wl[wm][ks], 72);
#pragma unroll
            for (int j = 0; j < 2; j++) {
                wmma::fragment<wmma::matrix_b, 16, 16, 16, __half, wmma::row_major> bh, bl;
                wmma::load_matrix_sync(bh, &s_vh[ks][wn + 16 * j], 72);
                wmma::load_matrix_sync(bl, &s_vl[ks][wn + 16 * j], 72);
                wmma::mma_sync(acc[j], ah, bh, acc[j]);
                wmma::mma_sync(acc[j], al, bh, acc[j]);
                wmma::mma_sync(acc[j], ah, bl, acc[j]);
            }
        }
    }
#pragma unroll
    for (int j = 0; j < 2; j++)
        wmma::store_matrix_sync(
            g_y + (size_t)(t0 + wm) * INTER + h * P_DIM + wn + 16 * j,
            acc[j], INTER, wmma::mem_row_major);
}

// ---------------- gated RMSNorm (b1 + D residual fused), fp16 hi/lo out ----------------
__global__ __launch_bounds__(256)
void gated_norm_kernel(const float* __restrict__ rmsw, const float* __restrict__ b1,
                       const float* __restrict__ Dp) {
    const int t = blockIdx.x;
    __shared__ float red[8];
    float vals[8];
    float local = 0.f;
#pragma unroll
    for (int i = 0; i < 8; i++) {
        int c = threadIdx.x + i * 256;
        float z = g_zx[(size_t)t * PROJ + c] + b1[c];
        float yv = g_y[(size_t)t * INTER + c] +
                   g_x[(size_t)t * INTER + c] * Dp[c >> 6];
        float gv = yv * silu_f(z);
        vals[i] = gv;
        local = fmaf(gv, gv, local);
    }
#pragma unroll
    for (int off = 16; off > 0; off >>= 1)
        local += __shfl_xor_sync(0xffffffffu, local, off);
    if ((threadIdx.x & 31) == 0) red[threadIdx.x >> 5] = local;
    __syncthreads();
    if (threadIdx.x < 8) {
        float v = red[threadIdx.x];
#pragma unroll
        for (int off = 4; off > 0; off >>= 1)
            v += __shfl_xor_sync(0xffu, v, off);
        if (threadIdx.x == 0) red[0] = v;
    }
    __syncthreads();
    const float inv = rsqrtf(red[0] / (float)INTER + EPSNRM);
#pragma unroll
    for (int i = 0; i < 8; i++) {
        int c = threadIdx.x + i * 256;
        float v = vals[i] * inv * rmsw[c];
        __half h, l; split_fp16(v, h, l);
        g_ynh[(size_t)t * INTER + c] = h;
        g_ynl[(size_t)t * INTER + c] = l;
    }
}

// ---------------- Launch ----------------
extern "C" void kernel_launch(void* const* d_in, const int* in_sizes, int n_in,
                              void* d_out, int out_size) {
    const float* hs    = (const float*)d_in[0];
    const float* w1    = (const float*)d_in[1];
    const float* b1    = (const float*)d_in[2];
    const float* cw    = (const float*)d_in[3];
    const float* dtb   = (const float*)d_in[4];
    const float* alog  = (const float*)d_in[5];
    const float* lpar  = (const float*)d_in[6];
    const float* Dp    = (const float*)d_in[7];
    const float* rmsw  = (const float*)d_in[8];
    const float* w2    = (const float*)d_in[9];
    const float* b2    = (const float*)d_in[10];
    const int*   lvl   = (const int*)d_in[11];
    float* out = (float*)d_out;

    float *zx, *scores;
    __half *hsh, *hsl, *w1p, *w2p, *Bm16, *Ch, *Cl, *ynh, *ynl;
    cudaGetSymbolAddress((void**)&zx, g_zx);
    cudaGetSymbolAddress((void**)&scores, g_scores);
    cudaGetSymbolAddress((void**)&hsh, g_hsh);  cudaGetSymbolAddress((void**)&hsl, g_hsl);
    cudaGetSymbolAddress((void**)&w1p, g_w1);   cudaGetSymbolAddress((void**)&w2p, g_w2);
    cudaGetSymbolAddress((void**)&Bm16, g_Bm16);
    cudaGetSymbolAddress((void**)&Ch, g_Ch);    cudaGetSymbolAddress((void**)&Cl, g_Cl);
    cudaGetSymbolAddress((void**)&ynh, g_ynh);  cudaGetSymbolAddress((void**)&ynl, g_ynl);

    // 0) operand conversion (8 elems/thread)
    split_pair_kernel<<<(T_LEN * HID / 8 + 255) / 256, 256>>>(hs, hsh, hsl, T_LEN * HID);
    cvt_fp16_kernel<<<(PROJ * HID / 8 + 255) / 256, 256>>>(w1, w1p, PROJ * HID);
    cvt_fp16_kernel<<<(HID * INTER / 8 + 255) / 256, 256>>>(w2, w2p, HID * INTER);

    // 1) in_proj
    gemm_fp16x2_nt<128><<<dim3(PROJ / 128, T_LEN / 128), 256>>>(hsh, hsl, w1p, zx,
                                                                T_LEN, PROJ, HID);

    // 2) dt / g / Ls (before conv: conv needs dt for the v split)
    prep_kernel<<<T_LEN, 128>>>(dtb, alog, lpar, b1);

    // 3) conv + silu + splits (x, v pair, B, C pair)
    conv_silu_kernel<<<(CONV_DIM * (T_LEN / 8) + 255) / 256, 256>>>(cw, b1);

    // 4) cumsum of g per head
    scan_kernel<<<H_HEADS, 1024>>>();

    // 5) scores[t,s] = C[t]·B[s]
    gemm_fp16x2_nt<64><<<dim3(T_LEN / 64, T_LEN / 128), 256>>>(Ch, Cl, Bm16, scores,
                                                               T_LEN, T_LEN, N_STATE);

    // 6) attention (tensor-core w@v, v via cp.async from precomputed pairs)
    attn_tc_kernel<<<dim3(T_LEN / 64, H_HEADS), 256>>>(lvl);

    // 7) gated RMSNorm (D residual + b1 fused)
    gated_norm_kernel<<<T_LEN, 256>>>(rmsw, b1, Dp);

    // 8) out_proj
    gemm_fp16x2_nt<64><<<dim3(HID / 64, T_LEN / 128), 256>>>(ynh, ynl, w2p, out,
                                                             T_LEN, HID, INTER);
    bias_add_kernel<<<(T_LEN * HID / 4 + 255) / 256, 256>>>(out, b2, HID, T_LEN * HID);
}

// round 16
// speedup vs baseline: 1.6817x; 1.0368x over previous
#include <cuda_runtime.h>
#include <cuda_bf16.h>
#include <cuda_fp16.h>
#include <mma.h>
#include <cstdint>
#include <cstdio>

using namespace nvcuda;

// ---------------- Problem constants ----------------
#define T_LEN   1024
#define HID     1024
#define H_HEADS 32
#define P_DIM   64
#define N_STATE 128
#define NL      15
#define KCONV   4
#define INTER   2048          // H*P
#define CONV_DIM 2304         // INTER + 2*N
#define PROJ    4864          // INTER + CONV_DIM + H*(NL+1)
#define DT_OFF  4352          // INTER + CONV_DIM
#define DL_OFF  4384          // DT_OFF + H
#define NCHEXT  (CONV_DIM + H_HEADS * NL)   // 2784: conv channels + Ls pseudo-channels
#define EPSNRM  1e-5f

// ---------------- Scratch (device globals; no allocation allowed) ----------------
__device__ float g_zx[T_LEN * PROJ];        // in_proj output (bias fused in consumers)
__device__ float g_x[T_LEN * INTER];        // conv+silu x part (unscaled)
__device__ float g_dt[T_LEN * H_HEADS];     // softplus dt, [t][h]
__device__ float g_cg[H_HEADS * T_LEN];     // cumsum of log-decay, [h][t]
__device__ float g_Ls[T_LEN * H_HEADS * NL];// level scales [t][h][l]
__device__ float g_scores[T_LEN * T_LEN];   // C·B^T (head-independent, G=1)
__device__ float g_y[T_LEN * INTER];        // attention output (D residual fused later)

// fp16 operands
__device__ __half g_hsh[T_LEN * HID],  g_hsl[T_LEN * HID];   // hs hi/lo
__device__ __half g_w1[PROJ * HID];                          // w1 single
__device__ __half g_w2[HID * INTER];                         // w2 single
__device__ __half g_Bm16[T_LEN * N_STATE];                   // keys single
__device__ __half g_Ch[T_LEN * N_STATE], g_Cl[T_LEN * N_STATE]; // queries hi/lo
__device__ __half g_ynh[T_LEN * INTER],  g_ynl[T_LEN * INTER];  // yn hi/lo
__device__ __half g_vh[T_LEN * INTER],   g_vl[T_LEN * INTER];   // v = x*dt hi/lo

__device__ __forceinline__ float softplus_f(float x) {
    return (x > 20.f) ? x : log1pf(expf(x));
}
__device__ __forceinline__ float silu_f(float x) {
    return x / (1.f + expf(-x));
}
__device__ __forceinline__ void split_fp16(float x, __half& h, __half& l) {
    h = __float2half(x);
    l = __float2half(x - __half2float(h));
}

#define CP_ASYNC16(smem_u32, gptr) \
    asm volatile("cp.async.cg.shared.global [%0], [%1], 16;\n" :: "r"(smem_u32), "l"(gptr))
#define CP_COMMIT() asm volatile("cp.async.commit_group;\n" ::: "memory")
#define CP_WAIT(n)  asm volatile("cp.async.wait_group %0;\n" :: "n"(n) : "memory")

// ---------------- ALL fp32->fp16 conversions in ONE kernel ----------------
// Segment 0: hs -> (hsh, hsl) pair.  Segment 1: w1 -> fp16.  Segment 2: w2 -> fp16.
#define CVT_N1 (T_LEN * HID / 8)
#define CVT_N2 (PROJ * HID / 8)
#define CVT_N3 (HID * INTER / 8)
__global__ void cvt_all_kernel(const float* __restrict__ hs,
                               const float* __restrict__ w1,
                               const float* __restrict__ w2) {
    int tid = blockIdx.x * blockDim.x + threadIdx.x;
    const float* src;
    __half *hi = nullptr, *lo = nullptr;
    int i;
    if (tid < CVT_N1) {
        i = tid * 8; src = hs; hi = g_hsh; lo = g_hsl;
    } else if (tid < CVT_N1 + CVT_N2) {
        i = (tid - CVT_N1) * 8; src = w1; hi = g_w1;
    } else if (tid < CVT_N1 + CVT_N2 + CVT_N3) {
        i = (tid - CVT_N1 - CVT_N2) * 8; src = w2; hi = g_w2;
    } else return;
    float4 a = *(const float4*)(src + i);
    float4 b = *(const float4*)(src + i + 4);
    const float v[8] = {a.x, a.y, a.z, a.w, b.x, b.y, b.z, b.w};
    __half hh[8], ll[8];
#pragma unroll
    for (int k = 0; k < 8; k++) {
        hh[k] = __float2half(v[k]);
        ll[k] = __float2half(v[k] - __half2float(hh[k]));
    }
    *(uint4*)(hi + i) = *(const uint4*)hh;
    if (lo) *(uint4*)(lo + i) = *(const uint4*)ll;
}

// ---------------- bias add (final output epilogue), float4 ----------------
__global__ void bias_add_kernel(float* __restrict__ C, const float* __restrict__ bias,
                                int N, int total) {
    int i = (blockIdx.x * blockDim.x + threadIdx.x) * 4;
    if (i >= total) return;
    float4 v = *(const float4*)(C + i);
    float4 bv = *(const float4*)(bias + (i % N));
    v.x += bv.x; v.y += bv.y; v.z += bv.z; v.w += bv.w;
    *(float4*)(C + i) = v;
}

// ---------------- Tensor-core NT GEMM, fp16 A-compensated x2 ----------------
template <int BN>
__global__ __launch_bounds__(256, 2)
void gemm_fp16x2_nt(const __half* __restrict__ Ah, const __half* __restrict__ Al,
                    const __half* __restrict__ B,
                    float* __restrict__ C, int M, int N, int K) {
    constexpr int NF = BN / 32;
    __shared__ __half sA[2][2][128][40];
    __shared__ __half sB[2][BN][40];
    const int tid = threadIdx.x;
    const int bm = blockIdx.y * 128, bn = blockIdx.x * BN;
    const int warp = tid >> 5;
    const int wm = (warp & 3) * 32;
    const int wn = (warp >> 2) * (BN / 2);

    wmma::fragment<wmma::accumulator, 16, 16, 16, float> acc[2][NF];
#pragma unroll
    for (int i = 0; i < 2; i++)
#pragma unroll
        for (int j = 0; j < NF; j++) wmma::fill_fragment(acc[i][j], 0.f);

    const int lr = tid >> 2;
    const int lc = (tid & 3) * 8;

    auto load_stage = [&](int k0, int buf) {
#pragma unroll
        for (int r = 0; r < 128; r += 64) {
            const size_t aoff = (size_t)(bm + lr + r) * K + k0 + lc;
            CP_ASYNC16((unsigned)__cvta_generic_to_shared(&sA[buf][0][lr + r][lc]), Ah + aoff);
            CP_ASYNC16((unsigned)__cvta_generic_to_shared(&sA[buf][1][lr + r][lc]), Al + aoff);
        }
#pragma unroll
        for (int r = 0; r < BN; r += 64) {
            const size_t boff = (size_t)(bn + lr + r) * K + k0 + lc;
            CP_ASYNC16((unsigned)__cvta_generic_to_shared(&sB[buf][lr + r][lc]), B + boff);
        }
    };

    load_stage(0, 0);
    CP_COMMIT();

    const int nt = K >> 5;
    for (int kt = 0; kt < nt; kt++) {
        const int buf = kt & 1;
        if (kt + 1 < nt) {
            load_stage((kt + 1) << 5, buf ^ 1);
            CP_COMMIT();
            CP_WAIT(1);
        } else {
            CP_WAIT(0);
        }
        __syncthreads();
#pragma unroll
        for (int ks = 0; ks < 32; ks += 16) {
            wmma::fragment<wmma::matrix_a, 16, 16, 16, __half, wmma::row_major> ah[2], al[2];
#pragma unroll
            for (int i = 0; i < 2; i++) {
                wmma::load_matrix_sync(ah[i], &sA[buf][0][wm + 16 * i][ks], 40);
                wmma::load_matrix_sync(al[i], &sA[buf][1][wm + 16 * i][ks], 40);
            }
#pragma unroll
            for (int j = 0; j < NF; j++) {
                wmma::fragment<wmma::matrix_b, 16, 16, 16, __half, wmma::col_major> bf;
                wmma::load_matrix_sync(bf, &sB[buf][wn + 16 * j][ks], 40);
                wmma::mma_sync(acc[0][j], ah[0], bf, acc[0][j]);
                wmma::mma_sync(acc[1][j], ah[1], bf, acc[1][j]);
                wmma::mma_sync(acc[0][j], al[0], bf, acc[0][j]);
                wmma::mma_sync(acc[1][j], al[1], bf, acc[1][j]);
            }
        }
        __syncthreads();
    }
#pragma unroll
    for (int i = 0; i < 2; i++)
#pragma unroll
        for (int j = 0; j < NF; j++)
            wmma::store_matrix_sync(C + (size_t)(bm + wm + 16 * i) * N + bn + wn + 16 * j,
                                    acc[i][j], N, wmma::mem_row_major);
}

// ---------------- scan: dt = softplus(...), g = -exp(A_log)*dt, cg = cumsum(g) ------
__global__ __launch_bounds__(1024)
void scan_kernel(const float* __restrict__ dt_bias,
                 const float* __restrict__ A_log,
                 const float* __restrict__ b1) {
    __shared__ float sh[T_LEN];
    const int h = blockIdx.x;
    const int t = threadIdx.x;
    const float bias = b1[DT_OFF + h] + dt_bias[h];
    const float nA = -expf(A_log[h]);
    float d = softplus_f(g_zx[(size_t)t * PROJ + DT_OFF + h] + bias);
    g_dt[t * H_HEADS + h] = d;
    sh[t] = nA * d;
    __syncthreads();
    for (int off = 1; off < T_LEN; off <<= 1) {
        float add = (t >= off) ? sh[t - off] : 0.f;
        __syncthreads();
        sh[t] += add;
        __syncthreads();
    }
    g_cg[h * T_LEN + t] = sh[t];
}

// ---------------- Depthwise conv (K=4) + SiLU + splits + Ls, 8 t/thread ----------------
// Channels [0, CONV_DIM): conv path (x, v pair, B, C pair).
// Channels [CONV_DIM, NCHEXT): Ls[t][i] = softplus(L_param[i] * (dl + b1)).
__global__ void conv_silu_kernel(const float* __restrict__ conv_w,
                                 const float* __restrict__ b1,
                                 const float* __restrict__ L_param) {
    int idx = blockIdx.x * blockDim.x + threadIdx.x;
    if (idx >= NCHEXT * (T_LEN / 8)) return;
    const int c  = idx % NCHEXT;
    const int t0 = (idx / NCHEXT) * 8;
    if (c >= CONV_DIM) {
        const int i = c - CONV_DIM;                 // 0..479 = h*NL + l
        const float lp = L_param[i];
        const float bb = b1[DL_OFF + i];
#pragma unroll
        for (int k = 0; k < 8; k++) {
            const int t = t0 + k;
            g_Ls[(size_t)t * (H_HEADS * NL) + i] =
                softplus_f(lp * (g_zx[(size_t)t * PROJ + DL_OFF + i] + bb));
        }
        return;
    }
    const float bias = b1[INTER + c];
    float w0 = conv_w[c * KCONV + 0], w1_ = conv_w[c * KCONV + 1];
    float w2_ = conv_w[c * KCONV + 2], w3 = conv_w[c * KCONV + 3];
    float win[11];
#pragma unroll
    for (int i = 0; i < 11; i++) {
        int ts = t0 - 3 + i;
        win[i] = (ts >= 0) ? g_zx[(size_t)ts * PROJ + INTER + c] + bias : 0.f;
    }
#pragma unroll
    for (int k = 0; k < 8; k++) {
        const int t = t0 + k;
        float acc = win[k] * w0 + win[k + 1] * w1_ + win[k + 2] * w2_ + win[k + 3] * w3;
        float s = silu_f(acc);
        if (c < INTER) {
            g_x[(size_t)t * INTER + c] = s;
            float v = s * g_dt[t * H_HEADS + (c >> 6)];
            __half h, l; split_fp16(v, h, l);
            g_vh[(size_t)t * INTER + c] = h;
            g_vl[(size_t)t * INTER + c] = l;
        } else if (c < INTER + N_STATE) {
            g_Bm16[t * N_STATE + (c - INTER)] = __float2half(s);
        } else {
            __half h, l; split_fp16(s, h, l);
            int o = t * N_STATE + (c - INTER - N_STATE);
            g_Ch[o] = h; g_Cl[o] = l;
        }
    }
}

// ---------------- Attention on tensor cores: per (head, t-tile of 64) ----------------
// Skip-scan hoisted: cg monotone decreasing => first live s-tile found once.
__global__ __launch_bounds__(256)
void attn_tc_kernel(const int* __restrict__ lvl) {
    const int h = blockIdx.y;
    const int t0 = blockIdx.x * 64;
    __shared__ __half s_wh[64][72], s_wl[64][72];
    __shared__ __half s_vh[64][72], s_vl[64][72];
    __shared__ float s_cgt[64], s_cgs[64];
    __shared__ float s_Lst[64][16];
    const int tid = threadIdx.x;
    const int warp = tid >> 5;
    const int wm = (warp & 3) * 16;      // 4 warps along t
    const int wn = (warp >> 2) * 32;     // 2 warps along p

    if (tid < 64) s_cgt[tid] = g_cg[h * T_LEN + t0 + tid];
    for (int i = tid; i < 64 * NL; i += 256) {
        int r = i / NL, l = i % NL;
        s_Lst[r][l] = g_Ls[((size_t)(t0 + r) * H_HEADS + h) * NL + l];
    }

    // first s-tile with non-negligible decay (uniform across block)
    const float cgt0 = g_cg[h * T_LEN + t0];
    int s_start = 0;
    while (s_start < t0 && cgt0 - g_cg[h * T_LEN + s_start + 63] < -30.f) s_start += 64;

    wmma::fragment<wmma::accumulator, 16, 16, 16, float> acc[2];
    wmma::fill_fragment(acc[0], 0.f);
    wmma::fill_fragment(acc[1], 0.f);

    for (int s0 = s_start; s0 <= t0; s0 += 64) {
        __syncthreads();   // protect smem from previous iteration's MMA reads
        if (tid < 64) s_cgs[tid] = g_cg[h * T_LEN + s0 + tid];
        // v tiles: async copy from precomputed fp16 pairs
        for (int i = tid; i < 512; i += 256) {
            int r = i >> 3, ch = (i & 7) * 8;
            const size_t goff = (size_t)(s0 + r) * INTER + h * P_DIM + ch;
            CP_ASYNC16((unsigned)__cvta_generic_to_shared(&s_vh[r][ch]), g_vh + goff);
            CP_ASYNC16((unsigned)__cvta_generic_to_shared(&s_vl[r][ch]), g_vl + goff);
        }
        CP_COMMIT();
        __syncthreads();
        // build w tile (fp16 pair)
        for (int i = tid; i < 64 * 64; i += 256) {
            int r = i >> 6, c = i & 63;
            int tg = t0 + r, sg = s0 + c;
            float w = 0.f;
            if (sg <= tg) {
                int L = lvl[(size_t)tg * T_LEN + sg];
                w = g_scores[(size_t)tg * T_LEN + sg] *
                    __expf(s_cgt[r] - s_cgs[c]) * s_Lst[r][L];
            }
            __half hh, ll; split_fp16(w, hh, ll);
            s_wh[r][c] = hh; s_wl[r][c] = ll;
        }
        CP_WAIT(0);
        __syncthreads();
        // acc += w @ v  (3-pass compensated)
#pragma unroll
        for (int ks = 0; ks < 64; ks += 16) {
            wmma::fragment<wmma::matrix_a, 16, 16, 16, __half, wmma::row_major> ah, al;
            wmma::load_matrix_sync(ah, &s_wh[wm][ks], 72);
            wmma::load_matrix_sync(al, &s_wl[wm][ks], 72);
#pragma unroll
            for (int j = 0; j < 2; j++) {
                wmma::fragment<wmma::matrix_b, 16, 16, 16, __half, wmma::row_major> bh, bl;
                wmma::load_matrix_sync(bh, &s_vh[ks][wn + 16 * j], 72);
                wmma::load_matrix_sync(bl, &s_vl[ks][wn + 16 * j], 72);
                wmma::mma_sync(acc[j], ah, bh, acc[j]);
                wmma::mma_sync(acc[j], al, bh, acc[j]);
                wmma::mma_sync(acc[j], ah, bl, acc[j]);
            }
        }
    }
#pragma unroll
    for (int j = 0; j < 2; j++)
        wmma::store_matrix_sync(
            g_y + (size_t)(t0 + wm) * INTER + h * P_DIM + wn + 16 * j,
            acc[j], INTER, wmma::mem_row_major);
}

// ---------------- gated RMSNorm (b1 + D residual fused), float4, fp16 hi/lo out ------
__global__ __launch_bounds__(256)
void gated_norm_kernel(const float* __restrict__ rmsw, const float* __restrict__ b1,
                       const float* __restrict__ Dp) {
    const int t = blockIdx.x;
    __shared__ float red[8];
    float4 vals[2];
    float local = 0.f;
#pragma unroll
    for (int it = 0; it < 2; it++) {
        const int c = (threadIdx.x + it * 256) * 4;
        float4 z4 = *(const float4*)(g_zx + (size_t)t * PROJ + c);
        float4 b4 = *(const float4*)(b1 + c);
        float4 y4 = *(const float4*)(g_y + (size_t)t * INTER + c);
        float4 x4 = *(const float4*)(g_x + (size_t)t * INTER + c);
        const float Dh = Dp[c >> 6];   // 4 elems share a head (64 per head)
        float gv[4];
        gv[0] = (y4.x + x4.x * Dh) * silu_f(z4.x + b4.x);
        gv[1] = (y4.y + x4.y * Dh) * silu_f(z4.y + b4.y);
        gv[2] = (y4.z + x4.z * Dh) * silu_f(z4.z + b4.z);
        gv[3] = (y4.w + x4.w * Dh) * silu_f(z4.w + b4.w);
        vals[it] = make_float4(gv[0], gv[1], gv[2], gv[3]);
#pragma unroll
        for (int k = 0; k < 4; k++) local = fmaf(gv[k], gv[k], local);
    }
#pragma unroll
    for (int off = 16; off > 0; off >>= 1)
        local += __shfl_xor_sync(0xffffffffu, local, off);
    if ((threadIdx.x & 31) == 0) red[threadIdx.x >> 5] = local;
    __syncthreads();
    if (threadIdx.x < 8) {
        float v = red[threadIdx.x];
#pragma unroll
        for (int off = 4; off > 0; off >>= 1)
            v += __shfl_xor_sync(0xffu, v, off);
        if (threadIdx.x == 0) red[0] = v;
    }
    __syncthreads();
    const float inv = rsqrtf(red[0] / (float)INTER + EPSNRM);
#pragma unroll
    for (int it = 0; it < 2; it++) {
        const int c = (threadIdx.x + it * 256) * 4;
        float4 w4 = *(const float4*)(rmsw + c);
        const float v[4] = {vals[it].x * inv * w4.x, vals[it].y * inv * w4.y,
                            vals[it].z * inv * w4.z, vals[it].w * inv * w4.w};
        __half hh[4], ll[4];
#pragma unroll
        for (int k = 0; k < 4; k++) split_fp16(v[k], hh[k], ll[k]);
        *(uint2*)(g_ynh + (size_t)t * INTER + c) = *(const uint2*)hh;
        *(uint2*)(g_ynl + (size_t)t * INTER + c) = *(const uint2*)ll;
    }
}

// ---------------- Launch ----------------
extern "C" void kernel_launch(void* const* d_in, const int* in_sizes, int n_in,
                              void* d_out, int out_size) {
    const float* hs    = (const float*)d_in[0];
    const float* w1    = (const float*)d_in[1];
    const float* b1    = (const float*)d_in[2];
    const float* cw    = (const float*)d_in[3];
    const float* dtb   = (const float*)d_in[4];
    const float* alog  = (const float*)d_in[5];
    const float* lpar  = (const float*)d_in[6];
    const float* Dp    = (const float*)d_in[7];
    const float* rmsw  = (const float*)d_in[8];
    const float* w2    = (const float*)d_in[9];
    const float* b2    = (const float*)d_in[10];
    const int*   lvl   = (const int*)d_in[11];
    float* out = (float*)d_out;

    float *zx, *scores;
    __half *hsh, *hsl, *w1p, *w2p, *Bm16, *Ch, *Cl, *ynh, *ynl;
    cudaGetSymbolAddress((void**)&zx, g_zx);
    cudaGetSymbolAddress((void**)&scores, g_scores);
    cudaGetSymbolAddress((void**)&hsh, g_hsh);  cudaGetSymbolAddress((void**)&hsl, g_hsl);
    cudaGetSymbolAddress((void**)&w1p, g_w1);   cudaGetSymbolAddress((void**)&w2p, g_w2);
    cudaGetSymbolAddress((void**)&Bm16, g_Bm16);
    cudaGetSymbolAddress((void**)&Ch, g_Ch);    cudaGetSymbolAddress((void**)&Cl, g_Cl);
    cudaGetSymbolAddress((void**)&ynh, g_ynh);  cudaGetSymbolAddress((void**)&ynl, g_ynl);

    // 0) all operand conversions, one launch
    {
        const int total = CVT_N1 + CVT_N2 + CVT_N3;
        cvt_all_kernel<<<(total + 255) / 256, 256>>>(hs, w1, w2);
    }

    // 1) in_proj
    gemm_fp16x2_nt<128><<<dim3(PROJ / 128, T_LEN / 128), 256>>>(hsh, hsl, w1p, zx,
                                                                T_LEN, PROJ, HID);

    // 2) dt + g + cg in one scan (before conv: conv needs dt for v split)
    scan_kernel<<<H_HEADS, 1024>>>(dtb, alog, b1);

    // 3) conv + silu + splits + Ls
    conv_silu_kernel<<<(NCHEXT * (T_LEN / 8) + 255) / 256, 256>>>(cw, b1, lpar);

    // 4) scores[t,s] = C[t]·B[s]
    gemm_fp16x2_nt<64><<<dim3(T_LEN / 64, T_LEN / 128), 256>>>(Ch, Cl, Bm16, scores,
                                                               T_LEN, T_LEN, N_STATE);

    // 5) attention (tensor-core w@v)
    attn_tc_kernel<<<dim3(T_LEN / 64, H_HEADS), 256>>>(lvl);

    // 6) gated RMSNorm (D residual + b1 fused)
    gated_norm_kernel<<<T_LEN, 256>>>(rmsw, b1, Dp);

    // 7) out_proj + bias
    gemm_fp16x2_nt<64><<<dim3(HID / 64, T_LEN / 128), 256>>>(ynh, ynl, w2p, out,
                                                             T_LEN, HID, INTER);
    bias_add_kernel<<<(T_LEN * HID / 4 + 255) / 256, 256>>>(out, b2, HID, T_LEN * HID);
}